// round 7
// baseline (speedup 1.0000x reference)
#include <cuda_runtime.h>

// SoftDepthShader: per-pixel softmax depth blend over K=50 raster slots.
// out[p] = (sum_k w_k * z_k + delta) / (sum_k w_k + delta)
//   mask_k = pix_to_face_k >= 0  (int32 on device)
//   prob_k = sigmoid(-dists_k/SIGMA) * mask_k
//   zinv_k = (ZFAR - z_k)/(ZFAR-ZNEAR) * mask_k
//   zmax   = max(max_k zinv_k, EPS)
//   w_k    = prob_k * exp((zinv_k - zmax)/GAMMA)
//   delta  = max(exp((EPS - zmax)/GAMMA), EPS)
//
// R7: pixel-PAIR processing with dense 16B-aligned float4/int4 loads.
// A pair is 400 B = 25 float4 per array; one 8-lane group per pair,
// 4 float4-slots per lane. Elements are attributed to pixel A/B by a
// per-element select (only slot 12 actually straddles the boundary).

#define KSLOTS  50
#define SLOT4   25     // float4 slots per PAIR per array

__global__ __launch_bounds__(256)
void soft_depth_kernel(const float4* __restrict__ zbuf,
                       const float4* __restrict__ dists,
                       const int4*   __restrict__ p2f,
                       float2* __restrict__ out,
                       int npair)
{
    const float INV_SIGMA  = 1e4f;
    const float INV_GAMMA  = 1e4f;
    const float ZFAR       = 100.0f;
    const float ZRANGE     = 99.0f;
    const float INV_ZRANGE = 1.0f / 99.0f;
    const float EPS        = 1e-10f;

    int tid = blockIdx.x * blockDim.x + threadIdx.x;
    int grp = tid >> 3;          // one 8-lane group handles one pixel pair
    int sub = tid & 7;
    if (grp >= npair) return;

    size_t base = (size_t)grp * SLOT4;

    float pr[16], zi[16];
    float zmaxA = 0.0f, zmaxB = 0.0f;

    #pragma unroll
    for (int i = 0; i < 4; i++) {
        int  s  = sub + 8 * i;
        bool in = (s < SLOT4);           // only lane 0 has a valid 4th slot
        float4 z = make_float4(0.f, 0.f, 0.f, 0.f);
        float4 d = make_float4(0.f, 0.f, 0.f, 0.f);
        int4   f = make_int4(-1, -1, -1, -1);
        if (in) {
            z = __ldcs(zbuf  + base + s);
            d = __ldcs(dists + base + s);
            f = __ldcs(p2f   + base + s);
        }
        int e0 = 4 * s;                  // element index of .x within the pair

        #pragma unroll
        for (int j = 0; j < 4; j++) {
            float zz = (j == 0) ? z.x : (j == 1) ? z.y : (j == 2) ? z.z : z.w;
            float dd = (j == 0) ? d.x : (j == 1) ? d.y : (j == 2) ? d.z : d.w;
            int   ff = (j == 0) ? f.x : (j == 1) ? f.y : (j == 2) ? f.z : f.w;
            float m    = (ff >= 0) ? 1.0f : 0.0f;
            float prob = m * __fdividef(1.0f, 1.0f + __expf(dd * INV_SIGMA));
            float zinv = (ZFAR - zz) * INV_ZRANGE * m;
            bool  isB  = (e0 + j) >= KSLOTS;
            zmaxA = fmaxf(zmaxA, isB ? 0.0f : zinv);
            zmaxB = fmaxf(zmaxB, isB ? zinv : 0.0f);
            pr[4*i + j] = prob;
            zi[4*i + j] = zinv;
        }
    }

    // 8-lane group max for both pixels
    #pragma unroll
    for (int o = 4; o; o >>= 1) {
        zmaxA = fmaxf(zmaxA, __shfl_xor_sync(0xffffffffu, zmaxA, o));
        zmaxB = fmaxf(zmaxB, __shfl_xor_sync(0xffffffffu, zmaxB, o));
    }
    zmaxA = fmaxf(zmaxA, EPS);
    zmaxB = fmaxf(zmaxB, EPS);

    float numA = 0.0f, denA = 0.0f, numB = 0.0f, denB = 0.0f;
    #pragma unroll
    for (int i = 0; i < 4; i++) {
        int e0 = 4 * (sub + 8 * i);
        #pragma unroll
        for (int j = 0; j < 4; j++) {
            bool  isB = (e0 + j) >= KSLOTS;
            float zm  = isB ? zmaxB : zmaxA;
            float v   = zi[4*i + j];
            float w   = pr[4*i + j] * __expf((v - zm) * INV_GAMMA);
            float zz  = fmaf(-v, ZRANGE, ZFAR);   // reconstruct z; w=0 if masked
            float wz  = w * zz;
            denA += isB ? 0.0f : w;
            denB += isB ? w    : 0.0f;
            numA += isB ? 0.0f : wz;
            numB += isB ? wz   : 0.0f;
        }
    }
    #pragma unroll
    for (int o = 4; o; o >>= 1) {
        denA += __shfl_xor_sync(0xffffffffu, denA, o);
        numA += __shfl_xor_sync(0xffffffffu, numA, o);
        denB += __shfl_xor_sync(0xffffffffu, denB, o);
        numB += __shfl_xor_sync(0xffffffffu, numB, o);
    }

    if (sub == 0) {
        float deltaA = fmaxf(__expf((EPS - zmaxA) * INV_GAMMA), EPS);
        float deltaB = fmaxf(__expf((EPS - zmaxB) * INV_GAMMA), EPS);
        float2 r;
        r.x = __fdividef(numA + deltaA, denA + deltaA);   // BG_BLUE = 1
        r.y = __fdividef(numB + deltaB, denB + deltaB);
        out[grp] = r;
    }
}

extern "C" void kernel_launch(void* const* d_in, const int* in_sizes, int n_in,
                              void* d_out, int out_size)
{
    const float4* zbuf  = (const float4*)d_in[0];
    const float4* dists = (const float4*)d_in[1];
    const int4*   p2f   = (const int4*)d_in[2];
    float2*       out   = (float2*)d_out;

    int npix  = in_sizes[0] / KSLOTS;              // 8*256*256 = 524288 (even)
    int npair = npix >> 1;                         // 262144
    int threads = 256;
    long long total = (long long)npair * 8;        // 8 threads per pair
    int blocks = (int)((total + threads - 1) / threads);

    soft_depth_kernel<<<blocks, threads>>>(zbuf, dists, p2f, out, npair);
}

// round 8
// speedup vs baseline: 1.1628x; 1.1628x over previous
#include <cuda_runtime.h>

// SoftDepthShader: per-pixel softmax depth blend over K=50 raster slots.
// out[p] = (sum_k w_k * z_k + delta) / (sum_k w_k + delta)
//   mask_k = pix_to_face_k >= 0  (int32 on device)
//   prob_k = sigmoid(-dists_k/SIGMA) * mask_k
//   zinv_k = (ZFAR - z_k)/(ZFAR-ZNEAR) * mask_k
//   zmax   = max(max_k zinv_k, EPS)
//   w_k    = prob_k * exp((zinv_k - zmax)/GAMMA)
//   delta  = max(exp((EPS - zmax)/GAMMA), EPS)
//
// R8 = R5 (best: 49.2us, DRAM 81.4% — at the LTS/DRAM ceiling) with the
// predicated tail load replaced by an unconditional clamped broadcast load
// of slot 24 (L1-resident duplicate; validity folded into the mask).
// float2/int2 loads, 8 lanes/pixel, 4 slots/lane, fast reciprocal sigmoid,
// z reconstructed from zinv in pass 2.

#define KSLOTS   50
#define SLOT2    25      // float2 slots per pixel
#define LANES_PP 8
#define SPL      4       // float2 slots per lane (ceil(25/8))

__global__ __launch_bounds__(256)
void soft_depth_kernel(const float2* __restrict__ zbuf,
                       const float2* __restrict__ dists,
                       const int2*   __restrict__ p2f,
                       float* __restrict__ out,
                       int npix)
{
    const float INV_SIGMA  = 1e4f;
    const float INV_GAMMA  = 1e4f;
    const float ZFAR       = 100.0f;
    const float ZRANGE     = 99.0f;
    const float INV_ZRANGE = 1.0f / 99.0f;
    const float EPS        = 1e-10f;

    int tid = blockIdx.x * blockDim.x + threadIdx.x;
    int pix = tid >> 3;         // /8
    int sub = tid & 7;
    if (pix >= npix) return;

    size_t base = (size_t)pix * SLOT2;
    const float2* zb = zbuf  + base;
    const float2* ds = dists + base;
    const int2*   pf = p2f   + base;

    float pr[2 * SPL], zi[2 * SPL];
    float zmax = 0.0f;

    #pragma unroll
    for (int i = 0; i < SPL; i++) {
        int s = sub + LANES_PP * i;
        // valid = s < SLOT2; clamp so the load is always in-bounds
        // (lanes 1-7, i=3 re-load slot 24: broadcast, L1-resident, no branch)
        float val = (s < SLOT2) ? 1.0f : 0.0f;
        int   sc  = (s < SLOT2) ? s : (SLOT2 - 1);
        float2 z = __ldcs(zb + sc);
        float2 d = __ldcs(ds + sc);
        int2   f = __ldcs(pf + sc);

        float m0 = ((f.x >= 0) ? 1.0f : 0.0f) * val;
        float m1 = ((f.y >= 0) ? 1.0f : 0.0f) * val;
        float p0 = m0 * __fdividef(1.0f, 1.0f + __expf(d.x * INV_SIGMA));
        float p1 = m1 * __fdividef(1.0f, 1.0f + __expf(d.y * INV_SIGMA));
        float v0 = (ZFAR - z.x) * INV_ZRANGE * m0;
        float v1 = (ZFAR - z.y) * INV_ZRANGE * m1;
        pr[2*i]   = p0;  zi[2*i]   = v0;
        pr[2*i+1] = p1;  zi[2*i+1] = v1;
        zmax = fmaxf(zmax, fmaxf(v0, v1));
    }

    // 8-lane group max (lanes of one pixel contiguous within warp)
    #pragma unroll
    for (int o = 4; o; o >>= 1)
        zmax = fmaxf(zmax, __shfl_xor_sync(0xffffffffu, zmax, o));
    zmax = fmaxf(zmax, EPS);

    float num = 0.0f, den = 0.0f;
    #pragma unroll
    for (int j = 0; j < 2 * SPL; j++) {
        float w = pr[j] * __expf((zi[j] - zmax) * INV_GAMMA);
        float z = fmaf(-zi[j], ZRANGE, ZFAR);  // reconstruct z; w=0 if masked
        den += w;
        num = fmaf(w, z, num);
    }
    #pragma unroll
    for (int o = 4; o; o >>= 1) {
        den += __shfl_xor_sync(0xffffffffu, den, o);
        num += __shfl_xor_sync(0xffffffffu, num, o);
    }

    if (sub == 0) {
        float delta = fmaxf(__expf((EPS - zmax) * INV_GAMMA), EPS);
        out[pix] = __fdividef(num + delta, den + delta);   // BG_BLUE = 1
    }
}

extern "C" void kernel_launch(void* const* d_in, const int* in_sizes, int n_in,
                              void* d_out, int out_size)
{
    const float2* zbuf  = (const float2*)d_in[0];
    const float2* dists = (const float2*)d_in[1];
    const int2*   p2f   = (const int2*)d_in[2];
    float*        out   = (float*)d_out;

    int npix = in_sizes[0] / KSLOTS;               // 8*256*256 = 524288
    int threads = 256;
    long long total = (long long)npix * LANES_PP;  // 8 threads per pixel
    int blocks = (int)((total + threads - 1) / threads);

    soft_depth_kernel<<<blocks, threads>>>(zbuf, dists, p2f, out, npix);
}

// round 9
// speedup vs baseline: 1.1745x; 1.0101x over previous
#include <cuda_runtime.h>

// SoftDepthShader: per-pixel softmax depth blend over K=50 raster slots.
// out[p] = (sum_k w_k * z_k + delta) / (sum_k w_k + delta)
//   mask_k = pix_to_face_k >= 0  (int32 on device)
//   prob_k = sigmoid(-dists_k/SIGMA) * mask_k
//   zinv_k = (ZFAR - z_k)/(ZFAR-ZNEAR) * mask_k
//   zmax   = max(max_k zinv_k, EPS)
//   w_k    = prob_k * exp((zinv_k - zmax)/GAMMA)
//   delta  = max(exp((EPS - zmax)/GAMMA), EPS)
//
// FINAL (R5 configuration — measured best: 49.2us wall, DRAM 81.4%).
// The kernel is at the memory roofline: 317 MB irreducible traffic at the
// ~6.45 TB/s achieved LTS/DRAM ceiling = 49.2us. float2/int2 vectorized
// loads, 8 lanes/pixel x 4 float2-slots/lane, fast reciprocal sigmoid,
// z reconstructed from zinv in pass 2 (masked slots have w=0), shfl
// reductions within the 8-lane pixel group.

#define KSLOTS   50
#define SLOT2    25      // float2 slots per pixel
#define LANES_PP 8
#define SPL      4       // slots per lane (ceil(25/8))

__global__ __launch_bounds__(256)
void soft_depth_kernel(const float2* __restrict__ zbuf,
                       const float2* __restrict__ dists,
                       const int2*   __restrict__ p2f,
                       float* __restrict__ out,
                       int npix)
{
    const float INV_SIGMA  = 1e4f;
    const float INV_GAMMA  = 1e4f;
    const float ZFAR       = 100.0f;
    const float ZRANGE     = 99.0f;
    const float INV_ZRANGE = 1.0f / 99.0f;
    const float EPS        = 1e-10f;

    int tid = blockIdx.x * blockDim.x + threadIdx.x;
    int pix = tid >> 3;         // /8
    int sub = tid & 7;
    if (pix >= npix) return;

    size_t base = (size_t)pix * SLOT2;
    const float2* zb = zbuf  + base;
    const float2* ds = dists + base;
    const int2*   pf = p2f   + base;

    float pr[2 * SPL], zi[2 * SPL];
    float zmax = 0.0f;

    #pragma unroll
    for (int i = 0; i < SPL; i++) {
        int s = sub + LANES_PP * i;
        bool in = (s < SLOT2);
        float2 z = make_float2(0.0f, 0.0f);
        float2 d = make_float2(0.0f, 0.0f);
        int2   f = make_int2(-1, -1);
        if (in) {
            z = __ldcs(zb + s);
            d = __ldcs(ds + s);
            f = __ldcs(pf + s);
        }
        float m0 = (f.x >= 0) ? 1.0f : 0.0f;
        float m1 = (f.y >= 0) ? 1.0f : 0.0f;
        float e0 = __expf(d.x * INV_SIGMA);
        float e1 = __expf(d.y * INV_SIGMA);
        float p0 = m0 * __fdividef(1.0f, 1.0f + e0);  // sigmoid(-d/sigma)*m
        float p1 = m1 * __fdividef(1.0f, 1.0f + e1);
        float v0 = (ZFAR - z.x) * INV_ZRANGE * m0;
        float v1 = (ZFAR - z.y) * INV_ZRANGE * m1;
        pr[2*i]   = p0;  zi[2*i]   = v0;
        pr[2*i+1] = p1;  zi[2*i+1] = v1;
        zmax = fmaxf(zmax, fmaxf(v0, v1));
    }

    // 8-lane group max (lanes of one pixel contiguous within warp)
    #pragma unroll
    for (int o = 4; o; o >>= 1)
        zmax = fmaxf(zmax, __shfl_xor_sync(0xffffffffu, zmax, o));
    zmax = fmaxf(zmax, EPS);

    float num = 0.0f, den = 0.0f;
    #pragma unroll
    for (int j = 0; j < 2 * SPL; j++) {
        float w = pr[j] * __expf((zi[j] - zmax) * INV_GAMMA);
        float z = fmaf(-zi[j], ZRANGE, ZFAR);  // reconstruct z; w=0 if masked
        den += w;
        num = fmaf(w, z, num);
    }
    #pragma unroll
    for (int o = 4; o; o >>= 1) {
        den += __shfl_xor_sync(0xffffffffu, den, o);
        num += __shfl_xor_sync(0xffffffffu, num, o);
    }

    if (sub == 0) {
        float delta = fmaxf(__expf((EPS - zmax) * INV_GAMMA), EPS);
        out[pix] = __fdividef(num + delta, den + delta);   // BG_BLUE = 1
    }
}

extern "C" void kernel_launch(void* const* d_in, const int* in_sizes, int n_in,
                              void* d_out, int out_size)
{
    const float2* zbuf  = (const float2*)d_in[0];
    const float2* dists = (const float2*)d_in[1];
    const int2*   p2f   = (const int2*)d_in[2];
    float*        out   = (float*)d_out;

    int npix = in_sizes[0] / KSLOTS;               // 8*256*256 = 524288
    int threads = 256;
    long long total = (long long)npix * LANES_PP;  // 8 threads per pixel
    int blocks = (int)((total + threads - 1) / threads);

    soft_depth_kernel<<<blocks, threads>>>(zbuf, dists, p2f, out, npix);
}